// round 1
// baseline (speedup 1.0000x reference)
#include <cuda_runtime.h>
#include <cstdint>

#define N_ACT 80
#define M_CON 85
#define NP1   81
#define PDHG_ITERS 200
#define POWER_ITERS 20

static __device__ __forceinline__ float warp_sum(float v) {
    #pragma unroll
    for (int off = 16; off > 0; off >>= 1)
        v += __shfl_xor_sync(0xffffffffu, v, off);
    return v;
}
static __device__ __forceinline__ float warp_min(float v) {
    #pragma unroll
    for (int off = 16; off > 0; off >>= 1)
        v = fminf(v, __shfl_xor_sync(0xffffffffu, v, off));
    return v;
}

__global__ __launch_bounds__(96, 3)
void acp_kernel(const float* __restrict__ xhat,
                const float* __restrict__ Aglob,
                const float* __restrict__ bglob,
                float* __restrict__ out)
{
    const int p   = blockIdx.x;
    const int t   = threadIdx.x;      // 0..95
    const int wid = t >> 5;
    const int lane = t & 31;

    // Staging of A with pitch 81 (odd stride -> conflict-free column reads).
    __shared__ float As[M_CON * 81];
    __shared__ __align__(16) float sh_vec[84];   // v / z_bar   (indices 0..80 used)
    __shared__ __align__(16) float sh_y[88];     // Gv / y      (indices 0..84 used)
    __shared__ float sh_d[M_CON];
    __shared__ float sh_red[3];
    __shared__ __align__(16) float sh_x0[N_ACT];
    __shared__ __align__(16) float sh_dv[N_ACT];

    const float* Ap = Aglob + (size_t)p * (M_CON * N_ACT);

    // ---- stage A into shared (coalesced) ----
    for (int i = t; i < M_CON * N_ACT; i += 96) {
        int r = i / N_ACT;
        int c = i - r * N_ACT;
        As[r * 81 + c] = Ap[i];
    }
    if (t < 88) sh_y[t] = 0.0f;
    if (t < 84) sh_vec[t] = (t < NP1) ? 1.0f : 0.0f;  // power-iter v0 = ones
    __syncthreads();

    // ---- register-resident G in both orientations ----
    float rowA[N_ACT];   // row t of A   (thread t < 85)
    float colA[M_CON];   // column t of G (thread t < 81; col 80 is d)
    float dval = 0.0f, bval = 0.0f;

    if (t < M_CON) {
        float s0 = 0.0f, s1 = 0.0f;
        #pragma unroll
        for (int k = 0; k < N_ACT; k++) {
            float a = As[t * 81 + k];
            rowA[k] = a;
            if (k & 1) s1 = fmaf(a, a, s1); else s0 = fmaf(a, a, s0);
        }
        dval = fmaxf(sqrtf(s0 + s1), 1e-12f);   // d = clip(||A_row||, 1e-12)
        sh_d[t] = dval;
        bval = bglob[(size_t)p * M_CON + t];
    }
    __syncthreads();
    if (t < N_ACT) {
        #pragma unroll
        for (int j = 0; j < M_CON; j++) colA[j] = As[j * 81 + t];
    } else if (t == N_ACT) {
        #pragma unroll
        for (int j = 0; j < M_CON; j++) colA[j] = sh_d[j];
    }

    // row dot:  rowG . sh_vec  over 81 terms (rowG[80] = dval)
    // col dot:  colA . sh_y    over 85 terms
    #define ROW_DOT(res, VEC)                                          \
    {                                                                  \
        float a0 = 0.0f, a1 = 0.0f;                                    \
        const float4* v4_ = reinterpret_cast<const float4*>(VEC);      \
        _Pragma("unroll")                                              \
        for (int q = 0; q < 20; q++) {                                 \
            float4 vv = v4_[q];                                        \
            a0 = fmaf(rowA[4*q+0], vv.x, a0);                          \
            a1 = fmaf(rowA[4*q+1], vv.y, a1);                          \
            a0 = fmaf(rowA[4*q+2], vv.z, a0);                          \
            a1 = fmaf(rowA[4*q+3], vv.w, a1);                          \
        }                                                              \
        res = a0 + a1 + dval * (VEC)[80];                              \
    }
    #define COL_DOT(res, VEC)                                          \
    {                                                                  \
        float a0 = 0.0f, a1 = 0.0f;                                    \
        const float4* v4_ = reinterpret_cast<const float4*>(VEC);      \
        _Pragma("unroll")                                              \
        for (int q = 0; q < 21; q++) {                                 \
            float4 vv = v4_[q];                                        \
            a0 = fmaf(colA[4*q+0], vv.x, a0);                          \
            a1 = fmaf(colA[4*q+1], vv.y, a1);                          \
            a0 = fmaf(colA[4*q+2], vv.z, a0);                          \
            a1 = fmaf(colA[4*q+3], vv.w, a1);                          \
        }                                                              \
        res = a0 + a1 + colA[84] * (VEC)[84];                          \
    }

    // ---- power iteration: v <- GT(G v) / ||GT(G v)|| ----
    for (int pi = 0; pi < POWER_ITERS; pi++) {
        if (t < M_CON) {
            float g; ROW_DOT(g, sh_vec);
            sh_y[t] = g;
        }
        __syncthreads();
        float w = 0.0f;
        if (t < NP1) { COL_DOT(w, sh_y); }
        float ss = warp_sum(w * w);
        if (lane == 0) sh_red[wid] = ss;
        __syncthreads();
        float nrm = sqrtf(sh_red[0] + sh_red[1] + sh_red[2]) + 1e-12f;
        if (t < NP1) sh_vec[t] = w / nrm;
        __syncthreads();
    }
    // L = ||G v||
    {
        float g = 0.0f;
        if (t < M_CON) { ROW_DOT(g, sh_vec); }
        float ss = warp_sum(g * g);
        if (lane == 0) sh_red[wid] = ss;
        __syncthreads();
    }
    const float Lnrm = sqrtf(sh_red[0] + sh_red[1] + sh_red[2]);
    const float tau  = 0.9f / fmaxf(Lnrm, 1e-6f);   // sigma == tau

    // ---- PDHG: 200 fixed iterations ----
    if (t < 88) sh_y[t] = 0.0f;     // y = 0
    float zv = 0.0f, yv = 0.0f;     // z = 0
    __syncthreads();

    for (int it = 0; it < PDHG_ITERS; it++) {
        if (t < NP1) {
            float gty; COL_DOT(gty, sh_y);
            float cterm = (t == N_ACT) ? -1.0f : 0.0f;
            float znew = fmaxf(zv - tau * (cterm + gty), 0.0f);
            sh_vec[t] = 2.0f * znew - zv;   // z_bar
            zv = znew;
        }
        __syncthreads();
        if (t < M_CON) {
            float gz; ROW_DOT(gz, sh_vec);
            yv = fmaxf(yv + tau * (gz - bval), 0.0f);
            sh_y[t] = yv;
        }
        __syncthreads();
    }

    // ---- alpha map ----
    if (t < N_ACT) {
        sh_x0[t] = zv;
        sh_dv[t] = xhat[(size_t)p * N_ACT + t] - zv;
    }
    __syncthreads();

    const float INF = __int_as_float(0x7f800000);
    float ai = INF;
    if (t < M_CON) {
        float x0a = 0.0f, x0b = 0.0f, da = 0.0f, db = 0.0f;
        const float4* x4 = reinterpret_cast<const float4*>(sh_x0);
        const float4* d4 = reinterpret_cast<const float4*>(sh_dv);
        #pragma unroll
        for (int q = 0; q < 20; q++) {
            float4 xv = x4[q];
            float4 dv = d4[q];
            x0a = fmaf(rowA[4*q+0], xv.x, x0a);
            x0b = fmaf(rowA[4*q+1], xv.y, x0b);
            x0a = fmaf(rowA[4*q+2], xv.z, x0a);
            x0b = fmaf(rowA[4*q+3], xv.w, x0b);
            da  = fmaf(rowA[4*q+0], dv.x, da);
            db  = fmaf(rowA[4*q+1], dv.y, db);
            da  = fmaf(rowA[4*q+2], dv.z, da);
            db  = fmaf(rowA[4*q+3], dv.w, db);
        }
        float ax0 = x0a + x0b;
        float ad  = da + db;
        float slack = fmaxf(bval - ax0, 0.0f);
        ai = (ad > 0.0f) ? (slack / (ad + 1e-12f)) : INF;
    }
    ai = warp_min(ai);
    if (lane == 0) sh_red[wid] = ai;
    __syncthreads();
    float alpha = fminf(sh_red[0], fminf(sh_red[1], sh_red[2]));
    if (!isfinite(alpha)) alpha = 1.0f;
    alpha = fminf(fmaxf(alpha - 1e-9f, 0.0f), 1.0f);

    if (t < N_ACT)
        out[(size_t)p * N_ACT + t] = fmaxf(sh_x0[t] + alpha * sh_dv[t], 0.0f);

    #undef ROW_DOT
    #undef COL_DOT
}

extern "C" void kernel_launch(void* const* d_in, const int* in_sizes, int n_in,
                              void* d_out, int out_size)
{
    const float* xhat = (const float*)d_in[0];
    const float* A    = (const float*)d_in[1];
    const float* b    = (const float*)d_in[2];
    float* out        = (float*)d_out;
    int P = in_sizes[0] / N_ACT;     // 64*16 = 1024 problems
    acp_kernel<<<P, 96>>>(xhat, A, b, out);
}

// round 2
// speedup vs baseline: 1.0123x; 1.0123x over previous
#include <cuda_runtime.h>
#include <cstdint>

#define N_ACT 80
#define M_CON 85
#define NP1   81
#define PDHG_ITERS 200
#define POWER_ITERS 20

static __device__ __forceinline__ float warp_sum(float v) {
    #pragma unroll
    for (int off = 16; off > 0; off >>= 1)
        v += __shfl_xor_sync(0xffffffffu, v, off);
    return v;
}
static __device__ __forceinline__ float warp_min(float v) {
    #pragma unroll
    for (int off = 16; off > 0; off >>= 1)
        v = fminf(v, __shfl_xor_sync(0xffffffffu, v, off));
    return v;
}

__global__ __launch_bounds__(96, 3)
void acp_kernel(const float* __restrict__ xhat,
                const float* __restrict__ Aglob,
                const float* __restrict__ bglob,
                float* __restrict__ out)
{
    const int p   = blockIdx.x;
    const int t   = threadIdx.x;      // 0..95
    const int wid = t >> 5;
    const int lane = t & 31;

    // Staging of A with pitch 81 (odd stride -> conflict-free column reads).
    __shared__ float As[M_CON * 81];
    __shared__ __align__(16) float sh_vec[84];   // v / z_bar   (indices 0..80 used)
    __shared__ __align__(16) float sh_y[88];     // Gv / y      (indices 0..84 used)
    __shared__ float sh_d[M_CON];
    __shared__ float sh_red[3];
    __shared__ __align__(16) float sh_x0[N_ACT];
    __shared__ __align__(16) float sh_dv[N_ACT];

    const float* Ap = Aglob + (size_t)p * (M_CON * N_ACT);

    // ---- stage A into shared (coalesced) ----
    for (int i = t; i < M_CON * N_ACT; i += 96) {
        int r = i / N_ACT;
        int c = i - r * N_ACT;
        As[r * 81 + c] = Ap[i];
    }
    if (t < 88) sh_y[t] = 0.0f;
    if (t < 84) sh_vec[t] = (t < NP1) ? 1.0f : 0.0f;  // power-iter v0 = ones
    __syncthreads();

    // ---- register-resident G in both orientations ----
    float rowA[N_ACT];   // row t of A   (thread t < 85)
    float colA[M_CON];   // column t of G (thread t < 81; col 80 is d)
    float dval = 0.0f, bval = 0.0f;

    if (t < M_CON) {
        float s0 = 0.0f, s1 = 0.0f;
        #pragma unroll
        for (int k = 0; k < N_ACT; k++) {
            float a = As[t * 81 + k];
            rowA[k] = a;
            if (k & 1) s1 = fmaf(a, a, s1); else s0 = fmaf(a, a, s0);
        }
        dval = fmaxf(sqrtf(s0 + s1), 1e-12f);   // d = clip(||A_row||, 1e-12)
        sh_d[t] = dval;
        bval = bglob[(size_t)p * M_CON + t];
    }
    __syncthreads();
    if (t < N_ACT) {
        #pragma unroll
        for (int j = 0; j < M_CON; j++) colA[j] = As[j * 81 + t];
    } else if (t == N_ACT) {
        #pragma unroll
        for (int j = 0; j < M_CON; j++) colA[j] = sh_d[j];
    }

    // row dot:  rowG . sh_vec  over 81 terms (rowG[80] = dval)
    // col dot:  colA . sh_y    over 85 terms
    #define ROW_DOT(res, VEC)                                          \
    {                                                                  \
        float a0 = 0.0f, a1 = 0.0f;                                    \
        const float4* v4_ = reinterpret_cast<const float4*>(VEC);      \
        _Pragma("unroll")                                              \
        for (int q = 0; q < 20; q++) {                                 \
            float4 vv = v4_[q];                                        \
            a0 = fmaf(rowA[4*q+0], vv.x, a0);                          \
            a1 = fmaf(rowA[4*q+1], vv.y, a1);                          \
            a0 = fmaf(rowA[4*q+2], vv.z, a0);                          \
            a1 = fmaf(rowA[4*q+3], vv.w, a1);                          \
        }                                                              \
        res = a0 + a1 + dval * (VEC)[80];                              \
    }
    #define COL_DOT(res, VEC)                                          \
    {                                                                  \
        float a0 = 0.0f, a1 = 0.0f;                                    \
        const float4* v4_ = reinterpret_cast<const float4*>(VEC);      \
        _Pragma("unroll")                                              \
        for (int q = 0; q < 21; q++) {                                 \
            float4 vv = v4_[q];                                        \
            a0 = fmaf(colA[4*q+0], vv.x, a0);                          \
            a1 = fmaf(colA[4*q+1], vv.y, a1);                          \
            a0 = fmaf(colA[4*q+2], vv.z, a0);                          \
            a1 = fmaf(colA[4*q+3], vv.w, a1);                          \
        }                                                              \
        res = a0 + a1 + colA[84] * (VEC)[84];                          \
    }

    // ---- power iteration: v <- GT(G v) / ||GT(G v)|| ----
    for (int pi = 0; pi < POWER_ITERS; pi++) {
        if (t < M_CON) {
            float g; ROW_DOT(g, sh_vec);
            sh_y[t] = g;
        }
        __syncthreads();
        float w = 0.0f;
        if (t < NP1) { COL_DOT(w, sh_y); }
        float ss = warp_sum(w * w);
        if (lane == 0) sh_red[wid] = ss;
        __syncthreads();
        float nrm = sqrtf(sh_red[0] + sh_red[1] + sh_red[2]) + 1e-12f;
        if (t < NP1) sh_vec[t] = w / nrm;
        __syncthreads();
    }
    // L = ||G v||
    {
        float g = 0.0f;
        if (t < M_CON) { ROW_DOT(g, sh_vec); }
        float ss = warp_sum(g * g);
        if (lane == 0) sh_red[wid] = ss;
        __syncthreads();
    }
    const float Lnrm = sqrtf(sh_red[0] + sh_red[1] + sh_red[2]);
    const float tau  = 0.9f / fmaxf(Lnrm, 1e-6f);   // sigma == tau

    // ---- PDHG: 200 fixed iterations ----
    if (t < 88) sh_y[t] = 0.0f;     // y = 0
    float zv = 0.0f, yv = 0.0f;     // z = 0
    __syncthreads();

    for (int it = 0; it < PDHG_ITERS; it++) {
        if (t < NP1) {
            float gty; COL_DOT(gty, sh_y);
            float cterm = (t == N_ACT) ? -1.0f : 0.0f;
            float znew = fmaxf(zv - tau * (cterm + gty), 0.0f);
            sh_vec[t] = 2.0f * znew - zv;   // z_bar
            zv = znew;
        }
        __syncthreads();
        if (t < M_CON) {
            float gz; ROW_DOT(gz, sh_vec);
            yv = fmaxf(yv + tau * (gz - bval), 0.0f);
            sh_y[t] = yv;
        }
        __syncthreads();
    }

    // ---- alpha map ----
    if (t < N_ACT) {
        sh_x0[t] = zv;
        sh_dv[t] = xhat[(size_t)p * N_ACT + t] - zv;
    }
    __syncthreads();

    const float INF = __int_as_float(0x7f800000);
    float ai = INF;
    if (t < M_CON) {
        float x0a = 0.0f, x0b = 0.0f, da = 0.0f, db = 0.0f;
        const float4* x4 = reinterpret_cast<const float4*>(sh_x0);
        const float4* d4 = reinterpret_cast<const float4*>(sh_dv);
        #pragma unroll
        for (int q = 0; q < 20; q++) {
            float4 xv = x4[q];
            float4 dv = d4[q];
            x0a = fmaf(rowA[4*q+0], xv.x, x0a);
            x0b = fmaf(rowA[4*q+1], xv.y, x0b);
            x0a = fmaf(rowA[4*q+2], xv.z, x0a);
            x0b = fmaf(rowA[4*q+3], xv.w, x0b);
            da  = fmaf(rowA[4*q+0], dv.x, da);
            db  = fmaf(rowA[4*q+1], dv.y, db);
            da  = fmaf(rowA[4*q+2], dv.z, da);
            db  = fmaf(rowA[4*q+3], dv.w, db);
        }
        float ax0 = x0a + x0b;
        float ad  = da + db;
        float slack = fmaxf(bval - ax0, 0.0f);
        ai = (ad > 0.0f) ? (slack / (ad + 1e-12f)) : INF;
    }
    ai = warp_min(ai);
    if (lane == 0) sh_red[wid] = ai;
    __syncthreads();
    float alpha = fminf(sh_red[0], fminf(sh_red[1], sh_red[2]));
    if (!isfinite(alpha)) alpha = 1.0f;
    alpha = fminf(fmaxf(alpha - 1e-9f, 0.0f), 1.0f);

    if (t < N_ACT)
        out[(size_t)p * N_ACT + t] = fmaxf(sh_x0[t] + alpha * sh_dv[t], 0.0f);

    #undef ROW_DOT
    #undef COL_DOT
}

extern "C" void kernel_launch(void* const* d_in, const int* in_sizes, int n_in,
                              void* d_out, int out_size)
{
    const float* xhat = (const float*)d_in[0];
    const float* A    = (const float*)d_in[1];
    const float* b    = (const float*)d_in[2];
    float* out        = (float*)d_out;
    int P = in_sizes[0] / N_ACT;     // 64*16 = 1024 problems
    acp_kernel<<<P, 96>>>(xhat, A, b, out);
}